// round 16
// baseline (speedup 1.0000x reference)
#include <cuda_runtime.h>

#define BB 2
#define NN 512
#define FF 64
#define H1 256
#define QT 2
#define KB 32          // keys per tile
#define P  64          // pairs per tile = QT*KB
#define PL 68          // g1T row pitch in floats (16B-aligned, conflict-free)
#define NTILE (NN / KB)

// smem layout (floats): g1T[256*PL] | ex4[P*4] | ext[P] | attn[P] | lnred[16]
#define SM_G1    0
#define SM_EX4   (H1 * PL)
#define SM_EXT   (SM_EX4 + P * 4)
#define SM_ATTN  (SM_EXT + P)
#define SM_LNRED (SM_ATTN + P)
#define SM_FLOATS (SM_LNRED + 16)

// ---------------- scratch ----------------
__device__ float g_Aq[BB * NN * H1];      // qs@Wa1[0:64] + ba1
__device__ float g_Ak[BB * NN * H1];      // ks@Wa1[64:128]
__device__ float g_vproj[BB * NN * FF];   // vs@Wv + bv
__device__ float g_gpart[BB * 16 * FF];   // pooled-max partials
__device__ float g_Wa2d[H1 * H1 * 2];     // Wa2 duplicated: [i][j][2] = (w,w)

// ---------------- helpers ----------------
__device__ __forceinline__ float gelu_t(float x) {
    float u = 0.7978845608028654f * x * fmaf(0.044715f, x * x, 1.0f);
    float e = exp2f(u * 2.885390081777927f);            // exp(2u)
    float t = 1.0f - __fdividef(2.0f, e + 1.0f);        // tanh(u)
    return 0.5f * x * (1.0f + t);
}

__device__ __forceinline__ float warp_sum(float v) {
    v += __shfl_xor_sync(0xffffffffu, v, 16);
    v += __shfl_xor_sync(0xffffffffu, v, 8);
    v += __shfl_xor_sync(0xffffffffu, v, 4);
    v += __shfl_xor_sync(0xffffffffu, v, 2);
    v += __shfl_xor_sync(0xffffffffu, v, 1);
    return v;
}

// ---------------- K0a: duplicate Wa2 into (w,w) pairs ----------------
__global__ void k_dup(const float* __restrict__ Wa2) {
    int idx = blockIdx.x * 256 + threadIdx.x;      // 0..65535
    float w = Wa2[idx];
    reinterpret_cast<float2*>(g_Wa2d)[idx] = make_float2(w, w);
}

// ---------------- K0b: fill invalid ctx rows with ln1_b ----------------
__global__ void k_fill(const int* __restrict__ valid_lens,
                       const float* __restrict__ ln1_b, float* __restrict__ out) {
    int idx = blockIdx.x * 256 + threadIdx.x;      // 0..65535
    int row = idx >> 6, d = idx & 63;
    int b = row >> 9, q = row & 511;
    if (q >= valid_lens[b]) out[row * FF + d] = ln1_b[d];
}

// ---------------- K1: precompute Aq, Ak, vproj ----------------
__global__ void k_pre(const float* __restrict__ qs, const float* __restrict__ ks,
                      const float* __restrict__ vs,
                      const float* __restrict__ Wa1, const float* __restrict__ ba1,
                      const float* __restrict__ Wv, const float* __restrict__ bv) {
    __shared__ float xs[4096];
    int t = threadIdx.x;
    int bid = blockIdx.x;

    if (bid < 128) {
        bool isQ = (bid < 64);
        int rb = (isQ ? bid : bid - 64) * 16;
        const float* src = isQ ? qs : ks;
        #pragma unroll
        for (int u = 0; u < 4; u++) xs[t + 256 * u] = src[rb * FF + t + 256 * u];
        __syncthreads();
        const float* W = Wa1 + (isQ ? 0 : FF) * H1;
        float acc[16];
        float binit = isQ ? ba1[t] : 0.0f;
        #pragma unroll
        for (int r = 0; r < 16; r++) acc[r] = binit;
        for (int f = 0; f < FF; f++) {
            float w = W[f * H1 + t];
            #pragma unroll
            for (int r = 0; r < 16; r++) acc[r] = fmaf(xs[r * FF + f], w, acc[r]);
        }
        float* dst = (isQ ? g_Aq : g_Ak) + rb * H1 + t;
        #pragma unroll
        for (int r = 0; r < 16; r++) dst[r * H1] = acc[r];
    } else {
        int rb = (bid - 128) * 64;
        #pragma unroll
        for (int u = 0; u < 16; u++) xs[t + 256 * u] = vs[rb * FF + t + 256 * u];
        __syncthreads();
        int d = t & 63, rq = t >> 6;
        float acc[16];
        float binit = bv[d];
        #pragma unroll
        for (int r = 0; r < 16; r++) acc[r] = binit;
        for (int f = 0; f < FF; f++) {
            float w = Wv[f * FF + d];
            #pragma unroll
            for (int r = 0; r < 16; r++) acc[r] = fmaf(xs[(rq * 16 + r) * FF + f], w, acc[r]);
        }
        #pragma unroll
        for (int r = 0; r < 16; r++) g_vproj[(rb + rq * 16 + r) * FF + d] = acc[r];
    }
}

// ---------------- K2: fused pair-MLP attention + ctx + LN ----------------
// mask[b,q,k] = (q < vl[b]) && (t_diff > 0); k axis unmasked in the einsum.
// Persistent over valid q-pair items only; 2 blocks/SM.
__global__ void __launch_bounds__(256, 2) k_main(
    const float* __restrict__ qs_s, const float* __restrict__ ks_s,
    const float* __restrict__ qs_t, const float* __restrict__ ks_t,
    const int* __restrict__ valid_lens,
    const float* __restrict__ Wa1,
    const float* __restrict__ ba2, const float* __restrict__ Wa3,
    const float* __restrict__ ba3,
    const float* __restrict__ ln1_s, const float* __restrict__ ln1_b,
    float* __restrict__ out)
{
    extern __shared__ float sm[];
    float* g1T    = sm + SM_G1;
    float4* ex4s  = reinterpret_cast<float4*>(sm + SM_EX4);
    float* exts   = sm + SM_EXT;
    float* attn_s = sm + SM_ATTN;
    float* lnred  = sm + SM_LNRED;

    int t = threadIdx.x;
    int lane = t & 31, wrp = t >> 5;
    int vl0 = valid_lens[0], vl1 = valid_lens[1];
    int nv0 = (vl0 + 1) >> 1, nv1 = (vl1 + 1) >> 1;
    int T = nv0 + nv1;

    int j = t;
    float w5[5];
    #pragma unroll
    for (int c = 0; c < 5; c++) w5[c] = Wa1[(2 * FF + c) * H1 + j];
    float ba3v = ba3[0];

    const float4* B24 = reinterpret_cast<const float4*>(ba2);
    const float4* W34 = reinterpret_cast<const float4*>(Wa3);
    const float* g1p = g1T + wrp * 8;     // warp owns pair octet wrp*8..+7

    for (int it = blockIdx.x; it < T; it += gridDim.x) {
        int b  = (it < nv0) ? 0 : 1;
        int q0 = ((it < nv0) ? it : it - nv0) * 2;
        int vl = b ? vl1 : vl0;

        float aq0 = g_Aq[(b * NN + q0) * H1 + j];
        float aq1 = g_Aq[(b * NN + q0 + 1) * H1 + j];
        float ctxacc = 0.0f;   // t<128: (qt=t>>6, d=t&63)

        for (int tile = 0; tile < NTILE; tile++) {
            int kbase = tile * KB;

            // ---- extras for 64 pairs ----
            if (t < P) {
                int qt = t >> 5, kk = t & 31;
                int q = q0 + qt, k = kbase + kk;
                float e0 = qs_s[(b * NN + q) * 2]     - ks_s[(b * NN + k) * 2];
                float e1 = qs_s[(b * NN + q) * 2 + 1] - ks_s[(b * NN + k) * 2 + 1];
                float d2 = e0 * e0 + e1 * e1;
                float e4 = qs_t[b * NN + q] - ks_t[b * NN + k];
                ex4s[t] = make_float4(e0, e1, sqrtf(d2), d2);
                exts[t] = e4;
            }
            __syncthreads();

            // ---- phase A: g1 = gelu(layer1) transposed [i=j][p] ----
            #pragma unroll 4
            for (int kk4 = 0; kk4 < 8; kk4++) {
                float a[4];
                #pragma unroll
                for (int r = 0; r < 4; r++)
                    a[r] = g_Ak[(b * NN + kbase + kk4 * 4 + r) * H1 + j];
                #pragma unroll
                for (int qt = 0; qt < 2; qt++) {
                    float aqv = qt ? aq1 : aq0;
                    float vv[4];
                    #pragma unroll
                    for (int r = 0; r < 4; r++) {
                        int p = qt * KB + kk4 * 4 + r;
                        float4 e = ex4s[p];
                        float et = exts[p];
                        float x = aqv + a[r];
                        x = fmaf(e.x, w5[0], x);
                        x = fmaf(e.y, w5[1], x);
                        x = fmaf(e.z, w5[2], x);
                        x = fmaf(e.w, w5[3], x);
                        x = fmaf(et,  w5[4], x);
                        vv[r] = gelu_t(x);
                    }
                    *reinterpret_cast<float4*>(&g1T[j * PL + qt * KB + kk4 * 4]) =
                        make_float4(vv[0], vv[1], vv[2], vv[3]);
                }
            }
            __syncthreads();

            // ---- GEMM: 2 j-sub-sweeps; thread = 8 pairs x 4 j (dup weights) ----
            float part[8];
            #pragma unroll
            for (int r = 0; r < 8; r++) part[r] = 0.0f;

            #pragma unroll 1
            for (int s = 0; s < 2; s++) {
                int wb = s * 32 + lane;              // j-quad index 0..63
                float4 ba2v = B24[wb];
                float4 wa3v = W34[wb];

                unsigned long long acc[16];
                #pragma unroll
                for (int r = 0; r < 16; r++) acc[r] = 0ULL;

                const ulonglong2* Wp = reinterpret_cast<const ulonglong2*>(g_Wa2d) + 2 * wb;
                ulonglong2 wb0[4], wb1[4];
                #pragma unroll
                for (int u = 0; u < 4; u++) { wb0[u] = Wp[u * 128]; wb1[u] = Wp[u * 128 + 1]; }

                #pragma unroll 1
                for (int ib = 0; ib < 64; ib++) {
                    #pragma unroll
                    for (int u = 0; u < 4; u++) {
                        int i = ib * 4 + u;
                        unsigned long long wd0 = wb0[u].x, wd1 = wb0[u].y;
                        unsigned long long wd2 = wb1[u].x, wd3 = wb1[u].y;
                        if (ib < 63) { wb0[u] = Wp[(i + 4) * 128]; wb1[u] = Wp[(i + 4) * 128 + 1]; }
                        ulonglong2 ga = *reinterpret_cast<const ulonglong2*>(g1p + i * PL);
                        ulonglong2 gb = *reinterpret_cast<const ulonglong2*>(g1p + i * PL + 4);
                        asm("fma.rn.f32x2 %0, %1, %2, %0;" : "+l"(acc[0])  : "l"(ga.x), "l"(wd0));
                        asm("fma.rn.f32x2 %0, %1, %2, %0;" : "+l"(acc[1])  : "l"(ga.y), "l"(wd0));
                        asm("fma.rn.f32x2 %0, %1, %2, %0;" : "+l"(acc[2])  : "l"(gb.x), "l"(wd0));
                        asm("fma.rn.f32x2 %0, %1, %2, %0;" : "+l"(acc[3])  : "l"(gb.y), "l"(wd0));
                        asm("fma.rn.f32x2 %0, %1, %2, %0;" : "+l"(acc[4])  : "l"(ga.x), "l"(wd1));
                        asm("fma.rn.f32x2 %0, %1, %2, %0;" : "+l"(acc[5])  : "l"(ga.y), "l"(wd1));
                        asm("fma.rn.f32x2 %0, %1, %2, %0;" : "+l"(acc[6])  : "l"(gb.x), "l"(wd1));
                        asm("fma.rn.f32x2 %0, %1, %2, %0;" : "+l"(acc[7])  : "l"(gb.y), "l"(wd1));
                        asm("fma.rn.f32x2 %0, %1, %2, %0;" : "+l"(acc[8])  : "l"(ga.x), "l"(wd2));
                        asm("fma.rn.f32x2 %0, %1, %2, %0;" : "+l"(acc[9])  : "l"(ga.y), "l"(wd2));
                        asm("fma.rn.f32x2 %0, %1, %2, %0;" : "+l"(acc[10]) : "l"(gb.x), "l"(wd2));
                        asm("fma.rn.f32x2 %0, %1, %2, %0;" : "+l"(acc[11]) : "l"(gb.y), "l"(wd2));
                        asm("fma.rn.f32x2 %0, %1, %2, %0;" : "+l"(acc[12]) : "l"(ga.x), "l"(wd3));
                        asm("fma.rn.f32x2 %0, %1, %2, %0;" : "+l"(acc[13]) : "l"(ga.y), "l"(wd3));
                        asm("fma.rn.f32x2 %0, %1, %2, %0;" : "+l"(acc[14]) : "l"(gb.x), "l"(wd3));
                        asm("fma.rn.f32x2 %0, %1, %2, %0;" : "+l"(acc[15]) : "l"(gb.y), "l"(wd3));
                    }
                }

                float bj[4] = {ba2v.x, ba2v.y, ba2v.z, ba2v.w};
                float wj[4] = {wa3v.x, wa3v.y, wa3v.z, wa3v.w};
                #pragma unroll
                for (int jj = 0; jj < 4; jj++) {
                    #pragma unroll
                    for (int pp2 = 0; pp2 < 4; pp2++) {
                        float lo, hi;
                        asm("mov.b64 {%0, %1}, %2;" : "=f"(lo), "=f"(hi) : "l"(acc[jj * 4 + pp2]));
                        part[pp2 * 2]     += gelu_t(lo + bj[jj]) * wj[jj];
                        part[pp2 * 2 + 1] += gelu_t(hi + bj[jj]) * wj[jj];
                    }
                }
            }

            // ---- reduce over 32 lanes, mask, write attn ----
            #pragma unroll
            for (int r = 0; r < 8; r++) part[r] = warp_sum(part[r]);
            if (lane == 0) {
                #pragma unroll
                for (int r = 0; r < 8; r++) {
                    int p = wrp * 8 + r;
                    int qt = p >> 5;
                    bool ok = ((q0 + qt) < vl) && (exts[p] > 0.0f);
                    attn_s[p] = ok ? (ba3v + part[r]) : 0.0f;
                }
            }
            __syncthreads();

            // ---- ctx accumulation ----
            if (t < 128) {
                int qt = t >> 6, d = t & 63;
                const float* vp = g_vproj + (b * NN + kbase) * FF + d;
                #pragma unroll 8
                for (int kk = 0; kk < KB; kk++)
                    ctxacc = fmaf(attn_s[qt * KB + kk], vp[kk * FF], ctxacc);
            }
            __syncthreads();
        }

        // ---- LayerNorm over d=64 per q-row ----
        float x = ctxacc;
        float s = warp_sum(x);
        if (lane == 0) lnred[wrp] = s;
        __syncthreads();
        int g2 = (t >> 6) & 3;
        float mu = (lnred[g2 * 2] + lnred[g2 * 2 + 1]) * (1.0f / 64.0f);
        float y = x - mu;
        float s2 = warp_sum(y * y);
        if (lane == 0) lnred[8 + wrp] = s2;
        __syncthreads();
        float var = (lnred[8 + g2 * 2] + lnred[8 + g2 * 2 + 1]) * (1.0f / 64.0f);
        if (t < 128) {
            int qt = t >> 6, d = t & 63;
            float o = y * rsqrtf(var + 1e-6f) * ln1_s[d] + ln1_b[d];
            out[(b * NN + q0 + qt) * FF + d] = o;
        }
        __syncthreads();
    }
}

// ---------------- K3: gate MLP + masked max-pool partials ----------------
__global__ void k_gate(const float* __restrict__ ctx, const int* __restrict__ valid_lens,
                       const float* __restrict__ Wg1, const float* __restrict__ bg1,
                       const float* __restrict__ Wg2, const float* __restrict__ bg2)
{
    __shared__ float ctx_s[32 * FF];
    __shared__ float hs[H1];
    __shared__ float gsum[4 * FF];
    int t = threadIdx.x;
    int b = blockIdx.x >> 4;
    int qg = blockIdx.x & 15;
    int qbase = qg * 32;
    int vl = valid_lens[b];
    #pragma unroll
    for (int u = 0; u < 8; u++)
        ctx_s[t + 256 * u] = ctx[(b * NN + qbase) * FF + t + 256 * u];
    __syncthreads();

    float lmax = -3.4e38f;
    for (int q = 0; q < 32; q++) {
        float a = bg1[t];
        #pragma unroll 8
        for (int f = 0; f < FF; f++) a = fmaf(ctx_s[q * FF + f], Wg1[f * H1 + t], a);
        hs[t] = gelu_t(a);
        __syncthreads();
        int d = t & 63, part = t >> 6;
        float s = 0.0f;
        #pragma unroll 8
        for (int jj = 0; jj < 64; jj++)
            s = fmaf(hs[part * 64 + jj], Wg2[(part * 64 + jj) * FF + d], s);
        gsum[part * FF + d] = s;
        __syncthreads();
        if (t < FF) {
            float g = bg2[t] + gsum[t] + gsum[FF + t] + gsum[2 * FF + t] + gsum[3 * FF + t];
            float gp = g * ctx_s[q * FF + t];
            float m = ((qbase + q) < vl) ? gp : -3.4e38f;
            lmax = fmaxf(lmax, m);
        }
        __syncthreads();
    }
    if (t < FF) g_gpart[(b * 16 + qg) * FF + t] = lmax;
}

// ---------------- K4: final max + LN -> vnode ----------------
__global__ void k_vnode(float* __restrict__ out,
                        const float* __restrict__ ln2_s, const float* __restrict__ ln2_b) {
    __shared__ float r4[4];
    int b = blockIdx.x, d = threadIdx.x;
    float m = -3.4e38f;
    #pragma unroll
    for (int g = 0; g < 16; g++) m = fmaxf(m, g_gpart[(b * 16 + g) * FF + d]);
    float s = warp_sum(m);
    if ((d & 31) == 0) r4[d >> 5] = s;
    __syncthreads();
    float mu = (r4[0] + r4[1]) * (1.0f / 64.0f);
    float y = m - mu;
    float s2 = warp_sum(y * y);
    if ((d & 31) == 0) r4[2 + (d >> 5)] = s2;
    __syncthreads();
    float var = (r4[2] + r4[3]) * (1.0f / 64.0f);
    out[BB * NN * FF + b * FF + d] = y * rsqrtf(var + 1e-6f) * ln2_s[d] + ln2_b[d];
}

// ---------------- launch ----------------
extern "C" void kernel_launch(void* const* d_in, const int* in_sizes, int n_in,
                              void* d_out, int out_size) {
    (void)in_sizes; (void)n_in; (void)out_size;
    const float* qs    = (const float*)d_in[0];
    const float* ks    = (const float*)d_in[1];
    const float* vs    = (const float*)d_in[2];
    const float* qs_s  = (const float*)d_in[3];
    const float* ks_s  = (const float*)d_in[4];
    const float* qs_t  = (const float*)d_in[5];
    const float* ks_t  = (const float*)d_in[6];
    const int*   vlen  = (const int*)  d_in[7];
    const float* Wv    = (const float*)d_in[8];
    const float* bv    = (const float*)d_in[9];
    const float* Wa1   = (const float*)d_in[10];
    const float* ba1   = (const float*)d_in[11];
    const float* Wa2   = (const float*)d_in[12];
    const float* ba2   = (const float*)d_in[13];
    const float* Wa3   = (const float*)d_in[14];
    const float* ba3   = (const float*)d_in[15];
    const float* Wg1   = (const float*)d_in[16];
    const float* bg1   = (const float*)d_in[17];
    const float* Wg2   = (const float*)d_in[18];
    const float* bg2   = (const float*)d_in[19];
    const float* ln1_s = (const float*)d_in[20];
    const float* ln1_b = (const float*)d_in[21];
    const float* ln2_s = (const float*)d_in[22];
    const float* ln2_b = (const float*)d_in[23];
    float* out = (float*)d_out;

    static int smem_set = 0;
    const int smem_bytes = SM_FLOATS * 4;   // ~71.3 KB -> 2 blocks/SM
    if (!smem_set) {
        cudaFuncSetAttribute(k_main, cudaFuncAttributeMaxDynamicSharedMemorySize, smem_bytes);
        smem_set = 1;
    }

    k_dup  <<<256, 256>>>(Wa2);
    k_fill <<<256, 256>>>(vlen, ln1_b, out);
    k_pre  <<<144, 256>>>(qs, ks, vs, Wa1, ba1, Wv, bv);
    k_main <<<296, 256, smem_bytes>>>(qs_s, ks_s, qs_t, ks_t, vlen,
                                      Wa1, ba2, Wa3, ba3, ln1_s, ln1_b, out);
    k_gate <<<32, 256>>>(out, vlen, Wg1, bg1, Wg2, bg2);
    k_vnode<<<BB, 64>>>(out, ln2_s, ln2_b);
}